// round 6
// baseline (speedup 1.0000x reference)
#include <cuda_runtime.h>
#include <math.h>

#define NVEC   350      // float4 per disease row (1400/4)
#define EPSF   1e-6f
#define MAXN   4096     // survival rows
#define IGRP   8        // i's per concordance block

// slotted accumulators: 128B stride -> each slot on its own L2 line
#define NSLOT  32
#define SSTRIDE 32
#define M_DIS  0
#define M_DCNT 1
#define M_TIME 2
#define M_RISK 3
#define M_RCNT 4
#define M_UNC  5
#define M_CONC 6
#define M_PAIR 7
#define NMET   8

// zero at module load; the finalizing block resets after reading, so every
// execution (correctness run + each graph replay) starts from zeros.
__device__ float        g_acc[NMET][NSLOT * SSTRIDE];
__device__ float2       g_tm[MAXN];        // packed (time_target, row_mean)
__device__ unsigned int g_done;

__device__ __forceinline__ void slot_add(int metric, int slot, float v) {
    atomicAdd(&g_acc[metric][slot * SSTRIDE], v);
}
// release-arrive: orders THIS thread's prior global ops; no L1 flush (unlike __threadfence)
__device__ __forceinline__ unsigned arrive_release(unsigned int* p) {
    unsigned old;
    asm volatile("atom.release.gpu.global.add.u32 %0, [%1], 1;"
                 : "=r"(old) : "l"(p) : "memory");
    return old;
}
__device__ __forceinline__ float ld_acq(const float* p) {
    float v;
    asm volatile("ld.acquire.gpu.global.f32 %0, [%1];" : "=f"(v) : "l"(p) : "memory");
    return v;
}

__device__ __forceinline__ float warp_sum(float v) {
    #pragma unroll
    for (int o = 16; o > 0; o >>= 1) v += __shfl_xor_sync(0xffffffff, v, o);
    return v;
}
__device__ __forceinline__ float warp_max(float v) {
    #pragma unroll
    for (int o = 16; o > 0; o >>= 1) v = fmaxf(v, __shfl_xor_sync(0xffffffff, v, o));
    return v;
}

// finalize, run by the globally-last block (of either kernel)
__device__ void try_finalize(int total_blocks, float* out, int n_tok) {
    __shared__ bool amLast;
    if (threadIdx.x == 0)
        amLast = (arrive_release(&g_done) == (unsigned)(total_blocks - 1));
    __syncthreads();
    if (!amLast) return;

    __shared__ float tot[NMET];
    if (threadIdx.x < NMET) {
        float s = 0.f;
        #pragma unroll
        for (int k = 0; k < NSLOT; k++)
            s += ld_acq(&g_acc[threadIdx.x][k * SSTRIDE]);
        tot[threadIdx.x] = s;
    }
    __syncthreads();
    if (threadIdx.x == 0) {
        float dcnt    = tot[M_DCNT] > 0.f ? tot[M_DCNT] : 1.f;
        float rcnt    = tot[M_RCNT] > 0.f ? tot[M_RCNT] : 1.f;
        float disease = tot[M_DIS] / dcnt;
        float timel   = -tot[M_TIME] / (float)n_tok;
        float riskl   = tot[M_RISK] / rcnt;
        float surv    = (tot[M_PAIR] > 0.f) ? 1.0f - tot[M_CONC] / tot[M_PAIR] : 0.0f;
        float u       = (tot[M_UNC] / (float)n_tok) * 0.01f;
        out[0] = disease;
        out[1] = timel;
        out[2] = riskl;
        out[3] = surv;
        out[4] = u;
        out[5] = disease + timel + riskl + surv + u;
        g_done = 0u;
    }
    for (int e = threadIdx.x; e < NMET * NSLOT; e += blockDim.x)
        g_acc[e / NSLOT][(e % NSLOT) * SSTRIDE] = 0.f;
}

// ---------------- stream2 kernel A: survival row means ----------------------
__global__ void __launch_bounds__(256) row_mean_kernel(
        const float* __restrict__ curves, const float* __restrict__ ttimes,
        int n, int T) {
    int w    = (blockIdx.x * blockDim.x + threadIdx.x) >> 5;
    int lane = threadIdx.x & 31;
    if (w >= n) return;
    const float* row = curves + (size_t)w * T;
    float s = 0.f;
    for (int k = lane; k < T; k += 32) s += row[k];
    s = warp_sum(s);
    if (lane == 0) g_tm[w] = make_float2(ttimes[w], s / (float)T);
}

// ---------------- stream2 kernel B: concordance (8-i register tile) ---------
__global__ void __launch_bounds__(256) concordance_kernel(
        const int* __restrict__ events, int n,
        int total_blocks, float* __restrict__ out, int n_tok) {
    int tid = threadIdx.x;
    int i0  = blockIdx.x * IGRP;

    __shared__ int sev[IGRP];
    if (tid < IGRP) sev[tid] = (i0 + tid < n) ? events[i0 + tid] : 0;
    __syncthreads();

    float ti[IGRP], mi[IGRP];
    bool  ev[IGRP];
    bool  any = false;
    #pragma unroll
    for (int k = 0; k < IGRP; k++) {
        float2 v = g_tm[i0 + k];
        ti[k] = v.x; mi[k] = v.y;
        ev[k] = (sev[k] == 1);
        any |= ev[k];
    }

    float conc = 0.f, cnt = 0.f;
    if (any) {
        // peel j in (i0, i0+IGRP): needs j > i0+k predicate
        if (tid < IGRP - 1) {
            int j = i0 + 1 + tid;
            if (j < n) {
                float2 jm = g_tm[j];
                for (int k = 0; k < j - i0; k++) {
                    if (ev[k] && ti[k] < jm.x) {
                        cnt  += 1.0f;
                        conc += (mi[k] < jm.y) ? 1.0f : ((mi[k] == jm.y) ? 0.5f : 0.0f);
                    }
                }
            }
        }
        // main sweep (L2-resident g_tm, 8 pairs per LDG.64)
        for (int j = i0 + IGRP + tid; j < n; j += 256) {
            float2 jm = __ldg(&g_tm[j]);
            float tj = jm.x, mj = jm.y;
            #pragma unroll
            for (int k = 0; k < IGRP; k++) {
                if (ev[k] && ti[k] < tj) {
                    cnt  += 1.0f;
                    conc += (mi[k] < mj) ? 1.0f : ((mi[k] == mj) ? 0.5f : 0.0f);
                }
            }
        }
    }

    conc = warp_sum(conc);
    cnt  = warp_sum(cnt);
    __shared__ float sc_[8], si_[8];
    int warp = tid >> 5;
    if ((tid & 31) == 0) { sc_[warp] = conc; si_[warp] = cnt; }
    __syncthreads();
    if (tid == 0) {
        float C = 0.f, P = 0.f;
        #pragma unroll
        for (int k = 0; k < 8; k++) { C += sc_[k]; P += si_[k]; }
        if (P > 0.f) {                      // thread 0 owns ALL global atomics
            int slot = blockIdx.x & (NSLOT - 1);
            slot_add(M_CONC, slot, C);
            slot_add(M_PAIR, slot, P);
        }
    }
    try_finalize(total_blocks, out, n_tok);
}

// ---------------- main-stream kernel: disease CE + small losses -------------
__global__ void __launch_bounds__(128) disease_ce_kernel(
        const float* __restrict__ logits, const int* __restrict__ targets,
        const float* __restrict__ tte, const float* __restrict__ ttgt,
        const float* __restrict__ risk, const int* __restrict__ rtgt,
        const float* __restrict__ unc,
        int total_blocks, float* __restrict__ out, int n_tok) {
    int row  = blockIdx.x;
    int t    = threadIdx.x;
    int slot = row & (NSLOT - 1);
    const float4* base = reinterpret_cast<const float4*>(logits) + (size_t)row * NVEC;

    float4 v0 = base[t];                  // t in [0,128) < 350
    float4 v1 = base[t + 128];            // < 350
    bool   h2 = (t + 256) < NVEC;         // t < 94
    float4 v2 = h2 ? base[t + 256]
                   : make_float4(-INFINITY, -INFINITY, -INFINITY, -INFINITY);

    __shared__ float sred[4];
    __shared__ float s_tval;
    __shared__ float s_small[3];          // time, unc, risk partials
    __shared__ int   s_rvalid;

    // idle-lane scalar losses -> smem (thread 0 commits all atomics later)
    if (t == 96) {
        float x    = tte[row];
        float rate = 1.0f / (x + EPSF);
        s_small[0] = __logf(rate + EPSF) - rate * ttgt[row];
        s_small[1] = unc[row];
    } else if (t == 64) {
        int r = rtgt[row];
        if (r >= 0) {
            const float* rl = risk + (size_t)row * 5;
            float a0 = rl[0], a1 = rl[1], a2 = rl[2], a3 = rl[3], a4 = rl[4];
            float mm = fmaxf(fmaxf(fmaxf(a0, a1), fmaxf(a2, a3)), a4);
            float ss = __expf(a0 - mm) + __expf(a1 - mm) + __expf(a2 - mm)
                     + __expf(a3 - mm) + __expf(a4 - mm);
            float xt = (r == 0) ? a0 : (r == 1) ? a1 : (r == 2) ? a2 : (r == 3) ? a3 : a4;
            s_small[2] = -(xt - mm - __logf(ss));
            s_rvalid   = 1;
        } else {
            s_small[2] = 0.f;
            s_rvalid   = 0;
        }
    }

    float m = fmaxf(fmaxf(fmaxf(v0.x, v0.y), fmaxf(v0.z, v0.w)),
                    fmaxf(fmaxf(v1.x, v1.y), fmaxf(v1.z, v1.w)));
    m = fmaxf(m, fmaxf(fmaxf(v2.x, v2.y), fmaxf(v2.z, v2.w)));

    int tgt = targets[row];
    if (tgt >= 0) {
        int vi = tgt >> 2;
        if ((vi & 127) == t) {
            float4 v = (vi < 128) ? v0 : ((vi < 256) ? v1 : v2);
            int l = tgt & 3;
            s_tval = (l == 0) ? v.x : (l == 1) ? v.y : (l == 2) ? v.z : v.w;
        }
    }

    m = warp_max(m);
    int warp = t >> 5;
    if ((t & 31) == 0) sred[warp] = m;
    __syncthreads();
    m = fmaxf(fmaxf(sred[0], sred[1]), fmaxf(sred[2], sred[3]));

    float s = __expf(v0.x - m) + __expf(v0.y - m) + __expf(v0.z - m) + __expf(v0.w - m)
            + __expf(v1.x - m) + __expf(v1.y - m) + __expf(v1.z - m) + __expf(v1.w - m);
    if (h2)
        s += __expf(v2.x - m) + __expf(v2.y - m) + __expf(v2.z - m) + __expf(v2.w - m);

    s = warp_sum(s);
    __syncthreads();
    if ((t & 31) == 0) sred[warp] = s;
    __syncthreads();

    if (t == 0) {                          // thread 0 owns ALL global atomics
        if (tgt >= 0) {
            float S   = sred[0] + sred[1] + sred[2] + sred[3];
            float nll = -(s_tval - m - __logf(S));
            slot_add(M_DIS,  slot, nll);
            slot_add(M_DCNT, slot, 1.0f);
        }
        slot_add(M_TIME, slot, s_small[0]);
        slot_add(M_UNC,  slot, s_small[1]);
        if (s_rvalid) {
            slot_add(M_RISK, slot, s_small[2]);
            slot_add(M_RCNT, slot, 1.0f);
        }
    }
    try_finalize(total_blocks, out, n_tok);
}

// ---------------- launch: fork-join, CE overlaps rowmean+concordance --------
extern "C" void kernel_launch(void* const* d_in, const int* in_sizes, int n_in,
                              void* d_out, int out_size) {
    const float* disease_logits = (const float*)d_in[0];
    const int*   disease_tgt    = (const int*)d_in[1];
    const float* tte            = (const float*)d_in[2];
    const float* ttgt           = (const float*)d_in[3];
    const float* risk           = (const float*)d_in[4];
    const int*   risk_tgt       = (const int*)d_in[5];
    const float* curves         = (const float*)d_in[6];
    const float* surv_tgt       = (const float*)d_in[7];
    const int*   events         = (const int*)d_in[8];
    const float* unc            = (const float*)d_in[9];
    float*       out            = (float*)d_out;

    int n_tok = in_sizes[1];            // 16384
    int n     = in_sizes[7];            // 4096
    int T     = in_sizes[6] / n;        // 120

    int conc_blocks  = (n + IGRP - 1) / IGRP;   // 512
    int total_blocks = n_tok + conc_blocks;     // finalize arrivals

    static cudaStream_t s2 = nullptr;
    static cudaEvent_t  eFork = nullptr, eJoin = nullptr;
    if (s2 == nullptr) {                // one-time resource setup (host objects)
        cudaStreamCreateWithFlags(&s2, cudaStreamNonBlocking);
        cudaEventCreateWithFlags(&eFork, cudaEventDisableTiming);
        cudaEventCreateWithFlags(&eJoin, cudaEventDisableTiming);
    }

    // fork s2 off the launch stream
    cudaEventRecord(eFork, 0);
    cudaStreamWaitEvent(s2, eFork, 0);

    // side chain: row means -> concordance
    row_mean_kernel<<<(n * 32 + 255) / 256, 256, 0, s2>>>(curves, surv_tgt, n, T);
    concordance_kernel<<<conc_blocks, 256, 0, s2>>>(events, n, total_blocks, out, n_tok);
    cudaEventRecord(eJoin, s2);

    // main chain: disease CE (runs concurrently with the side chain)
    disease_ce_kernel<<<n_tok, 128>>>(disease_logits, disease_tgt,
                                      tte, ttgt, risk, risk_tgt, unc,
                                      total_blocks, out, n_tok);

    // join so the graph's leaf depends on both chains
    cudaStreamWaitEvent(0, eJoin, 0);
}

// round 7
// speedup vs baseline: 1.4583x; 1.4583x over previous
#include <cuda_runtime.h>
#include <math.h>

#define NVEC   350      // float4 per disease row (1400/4)
#define EPSF   1e-6f
#define MAXN   4096     // survival rows
#define IGRP   8        // i's per concordance block

// slotted accumulators: 128B stride -> each slot on its own L2 line
#define NSLOT  32
#define SSTRIDE 32
#define M_DIS  0
#define M_DCNT 1
#define M_TIME 2
#define M_RISK 3
#define M_RCNT 4
#define M_UNC  5
#define M_CONC 6
#define M_PAIR 7
#define NMET   8

// zero at module load; the finalizing block resets after reading, so every
// execution (correctness run + each graph replay) starts from zeros.
__device__ float        g_acc[NMET][NSLOT * SSTRIDE];
__device__ float2       g_tm[MAXN];        // packed (time_target, row_mean)
__device__ unsigned int g_done;

__device__ __forceinline__ void slot_add(int metric, int slot, float v) {
    atomicAdd(&g_acc[metric][slot * SSTRIDE], v);
}

__device__ __forceinline__ float warp_sum(float v) {
    #pragma unroll
    for (int o = 16; o > 0; o >>= 1) v += __shfl_xor_sync(0xffffffff, v, o);
    return v;
}
__device__ __forceinline__ float warp_max(float v) {
    #pragma unroll
    for (int o = 16; o > 0; o >>= 1) v = fmaxf(v, __shfl_xor_sync(0xffffffff, v, o));
    return v;
}

// ---------------- kernel 1: disease CE + row means + small per-token losses --
__global__ void __launch_bounds__(128) disease_ce_kernel(
        const float* __restrict__ logits, const int* __restrict__ targets,
        const float* __restrict__ tte, const float* __restrict__ ttgt,
        const float* __restrict__ risk, const int* __restrict__ rtgt,
        const float* __restrict__ unc,
        const float* __restrict__ curves, const float* __restrict__ ttimes,
        int n_surv, int T) {
    int row  = blockIdx.x;
    int t    = threadIdx.x;
    int slot = row & (NSLOT - 1);
    const float4* base = reinterpret_cast<const float4*>(logits) + (size_t)row * NVEC;

    float4 v0 = base[t];                  // t in [0,128) < 350
    float4 v1 = base[t + 128];            // < 350
    bool   h2 = (t + 256) < NVEC;         // t < 94
    float4 v2 = h2 ? base[t + 256]
                   : make_float4(-INFINITY, -INFINITY, -INFINITY, -INFINITY);

    // ---- fused survival row mean: warp 1 handles row < n_surv ----
    if (row < n_surv && t >= 32 && t < 64) {
        int lane = t - 32;
        const float* crow = curves + (size_t)row * T;
        float s = 0.f;
        for (int k = lane; k < T; k += 32) s += crow[k];
        #pragma unroll
        for (int o = 16; o > 0; o >>= 1) s += __shfl_xor_sync(0xffffffff, s, o, 32);
        if (lane == 0) g_tm[row] = make_float2(ttimes[row], s / (float)T);
    }

    // ---- fused per-token scalar losses (idle-lane work) ----
    if (t == 96) {
        float x    = tte[row];
        float rate = 1.0f / (x + EPSF);
        float tl   = __logf(rate + EPSF) - rate * ttgt[row];
        slot_add(M_TIME, slot, tl);
        slot_add(M_UNC,  slot, unc[row]);
    } else if (t == 64) {
        int r = rtgt[row];
        if (r >= 0) {
            const float* rl = risk + (size_t)row * 5;
            float a0 = rl[0], a1 = rl[1], a2 = rl[2], a3 = rl[3], a4 = rl[4];
            float mm = fmaxf(fmaxf(fmaxf(a0, a1), fmaxf(a2, a3)), a4);
            float ss = __expf(a0 - mm) + __expf(a1 - mm) + __expf(a2 - mm)
                     + __expf(a3 - mm) + __expf(a4 - mm);
            float xt = (r == 0) ? a0 : (r == 1) ? a1 : (r == 2) ? a2 : (r == 3) ? a3 : a4;
            slot_add(M_RISK, slot, -(xt - mm - __logf(ss)));
            slot_add(M_RCNT, slot, 1.0f);
        }
    }

    float m = fmaxf(fmaxf(fmaxf(v0.x, v0.y), fmaxf(v0.z, v0.w)),
                    fmaxf(fmaxf(v1.x, v1.y), fmaxf(v1.z, v1.w)));
    m = fmaxf(m, fmaxf(fmaxf(v2.x, v2.y), fmaxf(v2.z, v2.w)));

    __shared__ float sred[4];
    __shared__ float s_tval;

    int tgt = targets[row];
    if (tgt >= 0) {
        int vi = tgt >> 2;
        if ((vi & 127) == t) {
            float4 v = (vi < 128) ? v0 : ((vi < 256) ? v1 : v2);
            int l = tgt & 3;
            s_tval = (l == 0) ? v.x : (l == 1) ? v.y : (l == 2) ? v.z : v.w;
        }
    }

    m = warp_max(m);
    int warp = t >> 5;
    if ((t & 31) == 0) sred[warp] = m;
    __syncthreads();
    m = fmaxf(fmaxf(sred[0], sred[1]), fmaxf(sred[2], sred[3]));

    float s = __expf(v0.x - m) + __expf(v0.y - m) + __expf(v0.z - m) + __expf(v0.w - m)
            + __expf(v1.x - m) + __expf(v1.y - m) + __expf(v1.z - m) + __expf(v1.w - m);
    if (h2)
        s += __expf(v2.x - m) + __expf(v2.y - m) + __expf(v2.z - m) + __expf(v2.w - m);

    s = warp_sum(s);
    __syncthreads();
    if ((t & 31) == 0) sred[warp] = s;
    __syncthreads();

    if (t == 0 && tgt >= 0) {
        float S   = sred[0] + sred[1] + sred[2] + sred[3];
        float nll = -(s_tval - m - __logf(S));
        slot_add(M_DIS,  slot, nll);
        slot_add(M_DCNT, slot, 1.0f);
    }
}

// ------- kernel 2: concordance via warp-ballot popcount + fused finalize ----
__global__ void __launch_bounds__(256) concordance_kernel(
        const int* __restrict__ events, int n,
        float* __restrict__ out, int n_tok) {
    int tid  = threadIdx.x;
    int lane = tid & 31;
    int wrp  = tid >> 5;
    int i0   = blockIdx.x * IGRP;

    __shared__ int sev[IGRP];
    if (tid < IGRP) sev[tid] = (i0 + tid < n) ? events[i0 + tid] : 0;
    __syncthreads();

    float ti[IGRP], mi[IGRP];
    bool  ev[IGRP];
    bool  any = false;
    #pragma unroll
    for (int k = 0; k < IGRP; k++) {
        float2 v = g_tm[i0 + k];           // L2 broadcast
        ti[k] = v.x; mi[k] = v.y;
        ev[k] = (sev[k] == 1);
        any |= ev[k];
    }

    unsigned cnt_i = 0, conc2_i = 0;       // conc scaled by 2 (0.5 -> 1)

    if (any) {
        // peel j in (i0, i0+IGRP): only thread 0 (<= 28 scalar ops)
        if (tid == 0) {
            for (int j = i0 + 1; j < i0 + IGRP && j < n; j++) {
                float2 jm = g_tm[j];
                for (int k = 0; k < j - i0; k++) {
                    if (ev[k] && ti[k] < jm.x) {
                        cnt_i++;
                        conc2_i += (mi[k] < jm.y) ? 2u : ((mi[k] == jm.y) ? 1u : 0u);
                    }
                }
            }
        }

        // main sweep: warp-cooperative, ballot+popc covers 32 pairs per k
        for (int jb = i0 + IGRP + wrp * 32; jb < n; jb += 256) {
            int j = jb + lane;
            float tj, mj;
            if (j < n) {
                float2 jm = __ldg(&g_tm[j]);
                tj = jm.x; mj = jm.y;
            } else {
                tj = -INFINITY; mj = 0.f;  // ti < -inf never true -> excluded
            }
            #pragma unroll
            for (int k = 0; k < IGRP; k++) {
                if (!ev[k]) continue;      // warp-uniform branch
                bool c1 = (ti[k] < tj);
                unsigned b1 = __ballot_sync(0xffffffff, c1);
                unsigned b2 = __ballot_sync(0xffffffff, c1 && (mi[k] < mj));
                unsigned b3 = __ballot_sync(0xffffffff, c1 && (mi[k] == mj));
                cnt_i   += __popc(b1);
                conc2_i += 2u * __popc(b2) + __popc(b3);
            }
        }
    }

    // cnt_i/conc2_i are warp-uniform (plus tid0's peel extras); reduce lane0s
    __shared__ unsigned sc_[8], si_[8];
    if (lane == 0) { sc_[wrp] = conc2_i; si_[wrp] = cnt_i; }
    __syncthreads();
    if (tid == 0) {
        unsigned C2 = 0, P = 0;
        #pragma unroll
        for (int k = 0; k < 8; k++) { C2 += sc_[k]; P += si_[k]; }
        if (P > 0) {
            int slot = blockIdx.x & (NSLOT - 1);
            slot_add(M_CONC, slot, 0.5f * (float)C2);
            slot_add(M_PAIR, slot, (float)P);
        }
    }

    // ---- last-done block finalizes and resets (512 blocks: cheap) ----
    __shared__ bool amLast;
    if (tid == 0) {
        __threadfence();
        unsigned v = atomicAdd(&g_done, 1u);
        amLast = (v == gridDim.x - 1);
    }
    __syncthreads();
    if (!amLast) return;

    __shared__ float tot[NMET];
    if (tid < NMET) {
        float s = 0.f;
        #pragma unroll
        for (int k = 0; k < NSLOT; k++) s += g_acc[tid][k * SSTRIDE];
        tot[tid] = s;
    }
    __syncthreads();
    if (tid == 0) {
        float dcnt    = tot[M_DCNT] > 0.f ? tot[M_DCNT] : 1.f;
        float rcnt    = tot[M_RCNT] > 0.f ? tot[M_RCNT] : 1.f;
        float disease = tot[M_DIS] / dcnt;
        float timel   = -tot[M_TIME] / (float)n_tok;
        float riskl   = tot[M_RISK] / rcnt;
        float surv    = (tot[M_PAIR] > 0.f) ? 1.0f - tot[M_CONC] / tot[M_PAIR] : 0.0f;
        float u       = (tot[M_UNC] / (float)n_tok) * 0.01f;
        out[0] = disease;
        out[1] = timel;
        out[2] = riskl;
        out[3] = surv;
        out[4] = u;
        out[5] = disease + timel + riskl + surv + u;
        g_done = 0u;
    }
    // reset accumulators for the next execution (256 threads, 256 entries)
    {
        int mtr = tid / NSLOT, s = tid % NSLOT;
        if (mtr < NMET) g_acc[mtr][s * SSTRIDE] = 0.f;
    }
}

// ---------------- launch ----------------
extern "C" void kernel_launch(void* const* d_in, const int* in_sizes, int n_in,
                              void* d_out, int out_size) {
    const float* disease_logits = (const float*)d_in[0];
    const int*   disease_tgt    = (const int*)d_in[1];
    const float* tte            = (const float*)d_in[2];
    const float* ttgt           = (const float*)d_in[3];
    const float* risk           = (const float*)d_in[4];
    const int*   risk_tgt       = (const int*)d_in[5];
    const float* curves         = (const float*)d_in[6];
    const float* surv_tgt       = (const float*)d_in[7];
    const int*   events         = (const int*)d_in[8];
    const float* unc            = (const float*)d_in[9];
    float*       out            = (float*)d_out;

    int n_tok = in_sizes[1];            // 16384
    int n     = in_sizes[7];            // 4096
    int T     = in_sizes[6] / n;        // 120

    disease_ce_kernel<<<n_tok, 128>>>(disease_logits, disease_tgt,
                                      tte, ttgt, risk, risk_tgt, unc,
                                      curves, surv_tgt, n, T);
    int conc_blocks = (n + IGRP - 1) / IGRP;   // 512
    concordance_kernel<<<conc_blocks, 256>>>(events, n, out, n_tok);
}